// round 17
// baseline (speedup 1.0000x reference)
#include <cuda_runtime.h>
#include <cuda_bf16.h>
#include <mma.h>
#include <cstdint>

using namespace nvcuda;

// ---------------- problem constants ----------------
#define MAX_N 100000
#define MAX_E 1700000
#define F_IN  256
#define F_MID 128
#define F_OUT 64
#define NBLK  148          // <= SM count; 1 CTA/SM -> co-residency guaranteed
#define NTHR  1024
#define NWARPS (NBLK * 32) // 4736 warps chip-wide

// dynamic smem: GEMM1 phase: (2*256 + 2*128) rows * 136 bf16 = 104448 bf16
// = 208896 bytes (< 227KB cap). GEMM2 phase needs 24832 floats = 99KB.
#define SMEM_BYTES 208896

// ---------------- device scratch (no allocations allowed) ----------------
__device__ int    g_deg[MAX_N];
__device__ float  g_dis[MAX_N];
__device__ int    g_rowptr[MAX_N + 1];
__device__ int    g_cursor[MAX_N];
__device__ int    g_bsum[128];
__device__ volatile unsigned g_bar_gen;   // monotonic, NEVER reset (replay-safe)
__device__ unsigned g_bar_cnt;
__device__ float2 g_cw[MAX_E];
// +128 rows pad: WMMA stores full 16-row blocks at the boundary tile
__device__ float  g_XW1[(size_t)(MAX_N + 128) * F_MID];
__device__ float  g_H[(size_t)MAX_N * F_MID];
__device__ float  g_HW2[(size_t)MAX_N * F_OUT];

// ---------------- packed f32x2 helpers (sm_103a) ----------------
__device__ __forceinline__ unsigned long long pack2(float x, float y) {
    unsigned long long r;
    asm("mov.b64 %0, {%1, %2};" : "=l"(r) : "f"(x), "f"(y));
    return r;
}
__device__ __forceinline__ void ffma2(unsigned long long& d,
                                      unsigned long long a,
                                      unsigned long long b) {
    asm("fma.rn.f32x2 %0, %1, %2, %0;" : "+l"(d) : "l"(a), "l"(b));
}
__device__ __forceinline__ float2 unpack2(unsigned long long v) {
    float lo, hi;
    asm("mov.b64 {%0, %1}, %2;" : "=f"(lo), "=f"(hi) : "l"(v));
    return make_float2(lo, hi);
}

// ---------------- grid barrier (all NBLK blocks co-resident) ----------------
__device__ __forceinline__ void gbar() {
    __syncthreads();
    if (threadIdx.x == 0) {
        __threadfence();
        unsigned gen = g_bar_gen;                       // read BEFORE arrive
        if (atomicAdd(&g_bar_cnt, 1u) == NBLK - 1u) {
            g_bar_cnt = 0u;                             // reset BEFORE release
            __threadfence();
            g_bar_gen = gen + 1u;                       // release
        } else {
            while (g_bar_gen == gen) { }                // spin (volatile read)
        }
        __threadfence();
    }
    __syncthreads();
}

// ---------------- the whole GCN in one persistent kernel ----------------
__global__ __launch_bounds__(NTHR, 1)
void k_gcn(const float* __restrict__ X,  const float* __restrict__ W1,
           const float* __restrict__ W2, const int* __restrict__ erow,
           const int* __restrict__ ecol, int E, int n,
           float* __restrict__ out) {
    extern __shared__ float smp[];
    const int tid = threadIdx.x;
    const int bid = blockIdx.x;
    const int lane = tid & 31;
    const int wid  = tid >> 5;
    const int gstride = NBLK * NTHR;      // 151552

    // ---- phase A: zero degrees ----
    for (int i = bid * NTHR + tid; i < n; i += gstride) g_deg[i] = 0;
    gbar();

    // ---- phase B: degree histogram ----
    for (int e = bid * NTHR + tid; e < E; e += gstride)
        atomicAdd(&g_deg[erow[e]], 1);
    gbar();

    // ---- phase C: dis + block-local scan (blocks 0..97, 1024 rows each) ----
    int v = 0, incl = 0;
    const int i_scan = bid * NTHR + tid;
    if (bid < 98) {
        int* s = (int*)smp;
        v = (i_scan < n) ? g_deg[i_scan] : 0;
        if (i_scan < n) g_dis[i_scan] = rsqrtf((float)v);
        s[tid] = v;
        __syncthreads();
#pragma unroll
        for (int off = 1; off < NTHR; off <<= 1) {
            int t = (tid >= off) ? s[tid - off] : 0;
            __syncthreads();
            s[tid] += t;
            __syncthreads();
        }
        incl = s[tid];
        if (tid == NTHR - 1) g_bsum[bid] = incl;
    }
    gbar();

    // ---- phase D: block offset + rowptr/cursor ----
    if (bid < 98) {
        int* s2 = (int*)smp;
        if (tid < 128) s2[tid] = (tid < bid) ? g_bsum[tid] : 0;
        __syncthreads();
        if (tid < 64) s2[tid] += s2[tid + 64];
        __syncthreads();
        if (tid < 32) {
            int t = s2[tid] + s2[tid + 32];
#pragma unroll
            for (int off = 16; off > 0; off >>= 1)
                t += __shfl_down_sync(0xffffffffu, t, off);
            if (tid == 0) s2[0] = t;
        }
        __syncthreads();
        int excl = s2[0] + incl - v;
        if (i_scan < n) {
            g_rowptr[i_scan] = excl;
            g_cursor[i_scan] = excl;
            if (i_scan == n - 1) g_rowptr[n] = excl + v;
        }
    }
    gbar();

    // ---- phase E: scatter edges into CSR ----
    for (int e = bid * NTHR + tid; e < E; e += gstride) {
        int r = erow[e];
        int c = ecol[e];
        int p = atomicAdd(&g_cursor[r], 1);
        g_cw[p] = make_float2(__int_as_float(c), g_dis[r] * g_dis[c]);
    }
    gbar();

    // ---- phase F: GEMM1 via WMMA bf16 3-term split (tensor cores) ----
    // g_XW1[n,128] = X[n,256] @ W1[256,128]
    // split: A*B ~= Ahi*Bhi + Ahi*Blo + Alo*Bhi (error ~1e-5)
    {
        __nv_bfloat16* Bhi = (__nv_bfloat16*)smp;      // [256][136]
        __nv_bfloat16* Blo = Bhi + 256 * 136;
        __nv_bfloat16* Ahi = Blo + 256 * 136;          // [128][136] (K-chunk)
        __nv_bfloat16* Alo = Ahi + 128 * 136;

        // convert W1 once: read float4 (4 cols), write uint2 (4 bf16)
        for (int t = tid; t < 256 * 32; t += NTHR) {
            int k  = t >> 5;
            int nv = (t & 31) * 4;
            float4 x4 = *(const float4*)&W1[(size_t)k * F_MID + nv];
            __nv_bfloat16 h0 = __float2bfloat16(x4.x);
            __nv_bfloat16 h1 = __float2bfloat16(x4.y);
            __nv_bfloat16 h2 = __float2bfloat16(x4.z);
            __nv_bfloat16 h3 = __float2bfloat16(x4.w);
            __nv_bfloat16 l0 = __float2bfloat16(x4.x - __bfloat162float(h0));
            __nv_bfloat16 l1 = __float2bfloat16(x4.y - __bfloat162float(h1));
            __nv_bfloat16 l2 = __float2bfloat16(x4.z - __bfloat162float(h2));
            __nv_bfloat16 l3 = __float2bfloat16(x4.w - __bfloat162float(h3));
            uint2 hv, lv;
            hv.x = (uint32_t)__bfloat16_as_ushort(h0)
                 | ((uint32_t)__bfloat16_as_ushort(h1) << 16);
            hv.y = (uint32_t)__bfloat16_as_ushort(h2)
                 | ((uint32_t)__bfloat16_as_ushort(h3) << 16);
            lv.x = (uint32_t)__bfloat16_as_ushort(l0)
                 | ((uint32_t)__bfloat16_as_ushort(l1) << 16);
            lv.y = (uint32_t)__bfloat16_as_ushort(l2)
                 | ((uint32_t)__bfloat16_as_ushort(l3) << 16);
            *(uint2*)&Bhi[k * 136 + nv] = hv;
            *(uint2*)&Blo[k * 136 + nv] = lv;
        }
        __syncthreads();

        const int wrow = wid >> 2;          // 0..7  -> m block (16 rows)
        const int wcol = (wid & 3) * 32;    // 0,32,64,96 -> n base (2x16)
        const int tiles = (n + 127) >> 7;

        for (int tile = bid; tile < tiles; tile += NBLK) {
            const int rowBase = tile << 7;
            wmma::fragment<wmma::accumulator, 16, 16, 16, float> acc[2];
            wmma::fill_fragment(acc[0], 0.f);
            wmma::fill_fragment(acc[1], 0.f);

#pragma unroll
            for (int chunk = 0; chunk < 2; chunk++) {
                // convert A chunk: 128 rows x 128 k
                for (int t = tid; t < 128 * 32; t += NTHR) {
                    int r  = t >> 5;
                    int kl = (t & 31) * 4;
                    int gr = rowBase + r;
                    float4 x4 = make_float4(0.f, 0.f, 0.f, 0.f);
                    if (gr < n)
                        x4 = *(const float4*)&X[(size_t)gr * F_IN + chunk * 128 + kl];
                    __nv_bfloat16 h0 = __float2bfloat16(x4.x);
                    __nv_bfloat16 h1 = __float2bfloat16(x4.y);
                    __nv_bfloat16 h2 = __float2bfloat16(x4.z);
                    __nv_bfloat16 h3 = __float2bfloat16(x4.w);
                    __nv_bfloat16 l0 = __float2bfloat16(x4.x - __bfloat162float(h0));
                    __nv_bfloat16 l1 = __float2bfloat16(x4.y - __bfloat162float(h1));
                    __nv_bfloat16 l2 = __float2bfloat16(x4.z - __bfloat162float(h2));
                    __nv_bfloat16 l3 = __float2bfloat16(x4.w - __bfloat162float(h3));
                    uint2 hv, lv;
                    hv.x = (uint32_t)__bfloat16_as_ushort(h0)
                         | ((uint32_t)__bfloat16_as_ushort(h1) << 16);
                    hv.y = (uint32_t)__bfloat16_as_ushort(h2)
                         | ((uint32_t)__bfloat16_as_ushort(h3) << 16);
                    lv.x = (uint32_t)__bfloat16_as_ushort(l0)
                         | ((uint32_t)__bfloat16_as_ushort(l1) << 16);
                    lv.y = (uint32_t)__bfloat16_as_ushort(l2)
                         | ((uint32_t)__bfloat16_as_ushort(l3) << 16);
                    *(uint2*)&Ahi[r * 136 + kl] = hv;
                    *(uint2*)&Alo[r * 136 + kl] = lv;
                }
                __syncthreads();

#pragma unroll
                for (int ks = 0; ks < 8; ks++) {
                    wmma::fragment<wmma::matrix_a, 16, 16, 16, __nv_bfloat16,
                                   wmma::row_major> ah, al;
                    wmma::load_matrix_sync(ah, &Ahi[wrow * 16 * 136 + ks * 16], 136);
                    wmma::load_matrix_sync(al, &Alo[wrow * 16 * 136 + ks * 16], 136);
                    const int krow = chunk * 128 + ks * 16;
#pragma unroll
                    for (int c = 0; c < 2; c++) {
                        wmma::fragment<wmma::matrix_b, 16, 16, 16, __nv_bfloat16,
                                       wmma::row_major> bh, bl;
                        wmma::load_matrix_sync(bh, &Bhi[krow * 136 + wcol + c * 16], 136);
                        wmma::load_matrix_sync(bl, &Blo[krow * 136 + wcol + c * 16], 136);
                        wmma::mma_sync(acc[c], ah, bh, acc[c]);
                        wmma::mma_sync(acc[c], ah, bl, acc[c]);
                        wmma::mma_sync(acc[c], al, bh, acc[c]);
                    }
                }
                __syncthreads();
            }
            // store 16x32 slab (g_XW1 padded by 128 rows -> no OOB)
            wmma::store_matrix_sync(
                &g_XW1[(size_t)(rowBase + wrow * 16) * F_MID + wcol],
                acc[0], F_MID, wmma::mem_row_major);
            wmma::store_matrix_sync(
                &g_XW1[(size_t)(rowBase + wrow * 16) * F_MID + wcol + 16],
                acc[1], F_MID, wmma::mem_row_major);
        }
    }
    gbar();

    // ---- phase G: SPMM1 + relu  g_H = relu(Ahat @ g_XW1) ----
    {
        const float4* base = (const float4*)g_XW1;     // row stride 32 f4
        const int gw = bid * 32 + wid;
        for (int row = gw; row < n; row += NWARPS) {
            int s = g_rowptr[row];
            int e = g_rowptr[row + 1];
            float4 acc = make_float4(0.f, 0.f, 0.f, 0.f);
            int i = s;
            for (; i + 7 < e; i += 8) {
                float2 cw[8];
#pragma unroll
                for (int u = 0; u < 8; u++) cw[u] = __ldg(&g_cw[i + u]);
                float4 vv[8];
#pragma unroll
                for (int u = 0; u < 8; u++)
                    vv[u] = __ldg(&base[((unsigned)__float_as_int(cw[u].x) << 5) + lane]);
#pragma unroll
                for (int u = 0; u < 8; u++) {
                    acc.x += cw[u].y * vv[u].x;
                    acc.y += cw[u].y * vv[u].y;
                    acc.z += cw[u].y * vv[u].z;
                    acc.w += cw[u].y * vv[u].w;
                }
            }
            if (i + 3 < e) {
                float2 cw[4];
#pragma unroll
                for (int u = 0; u < 4; u++) cw[u] = __ldg(&g_cw[i + u]);
                float4 vv[4];
#pragma unroll
                for (int u = 0; u < 4; u++)
                    vv[u] = __ldg(&base[((unsigned)__float_as_int(cw[u].x) << 5) + lane]);
#pragma unroll
                for (int u = 0; u < 4; u++) {
                    acc.x += cw[u].y * vv[u].x;
                    acc.y += cw[u].y * vv[u].y;
                    acc.z += cw[u].y * vv[u].z;
                    acc.w += cw[u].y * vv[u].w;
                }
                i += 4;
            }
            for (; i < e; i++) {
                float2 cw = __ldg(&g_cw[i]);
                float4 vv = __ldg(&base[((unsigned)__float_as_int(cw.x) << 5) + lane]);
                acc.x += cw.y * vv.x; acc.y += cw.y * vv.y;
                acc.z += cw.y * vv.z; acc.w += cw.y * vv.w;
            }
            acc.x = fmaxf(acc.x, 0.f); acc.y = fmaxf(acc.y, 0.f);
            acc.z = fmaxf(acc.z, 0.f); acc.w = fmaxf(acc.w, 0.f);
            ((float4*)g_H)[(unsigned)row * 32u + lane] = acc;
        }
    }
    gbar();

    // ---- phase H: GEMM2  g_HW2[n,64] = g_H[n,128] @ W2[128,64] ----
    // W2 smem-resident; ping-pong prefetch; BM=256, BK=32, TM=4, TN=4 (f32x2).
    {
        float* Ws = smp;                 // [128][64] = 8192 floats
        float* As = smp + 8192;          // 2 x [32][260] = 2 x 8320
        const int tx = tid & 15;         // *4 -> 64 cols
        const int ty = tid >> 4;         // *4 -> 256 rows
        const int ar = tid >> 3;         // A fill row (0..127), +128 for 2nd
        const int akv = tid & 7;
        const int tiles = (n + 255) >> 8;

        for (int i = tid; i < 8192 / 4; i += NTHR)
            ((float4*)Ws)[i] = ((const float4*)W2)[i];

        for (int tile = bid; tile < tiles; tile += NBLK) {
            const int rowBase = tile << 8;
            const int gr0 = rowBase + ar;
            const int gr1 = rowBase + ar + 128;
            unsigned long long acc2[4][2];
#pragma unroll
            for (int i = 0; i < 4; i++) { acc2[i][0] = 0ull; acc2[i][1] = 0ull; }

            float4 pa0 = make_float4(0.f, 0.f, 0.f, 0.f);
            float4 pa1 = make_float4(0.f, 0.f, 0.f, 0.f);
            if (gr0 < n) pa0 = *(const float4*)&g_H[(size_t)gr0 * F_MID + akv * 4];
            if (gr1 < n) pa1 = *(const float4*)&g_H[(size_t)gr1 * F_MID + akv * 4];
            __syncthreads();
            {
                float* A0 = As + (akv * 4) * 260 + ar;
                A0[0]         = pa0.x;  A0[260]       = pa0.y;
                A0[520]       = pa0.z;  A0[780]       = pa0.w;
                A0[128]       = pa1.x;  A0[260 + 128] = pa1.y;
                A0[520 + 128] = pa1.z;  A0[780 + 128] = pa1.w;
            }
            __syncthreads();

            int buf = 0;
#pragma unroll
            for (int k0 = 0; k0 < F_MID; k0 += 32) {
                if (k0 + 32 < F_MID) {
                    if (gr0 < n)
                        pa0 = *(const float4*)&g_H[(size_t)gr0 * F_MID + (k0 + 32) + akv * 4];
                    if (gr1 < n)
                        pa1 = *(const float4*)&g_H[(size_t)gr1 * F_MID + (k0 + 32) + akv * 4];
                }
                const float* Ab = As + buf * 8320;
#pragma unroll
                for (int k = 0; k < 32; k++) {
                    float4 ra = *(const float4*)&Ab[k * 260 + ty * 4];
                    const unsigned long long* rb =
                        (const unsigned long long*)&Ws[(k0 + k) * 64 + tx * 4];
                    unsigned long long b01 = rb[0], b23 = rb[1];
                    unsigned long long a;
                    a = pack2(ra.x, ra.x); ffma2(acc2[0][0], a, b01); ffma2(acc2[0][1], a, b23);
                    a = pack2(ra.y, ra.y); ffma2(acc2[1][0], a, b01); ffma2(acc2[1][1], a, b23);
                    a = pack2(ra.z, ra.z); ffma2(acc2[2][0], a, b01); ffma2(acc2[2][1], a, b23);
                    a = pack2(ra.w, ra.w); ffma2(acc2[3][0], a, b01); ffma2(acc2[3][1], a, b23);
                }
                if (k0 + 32 < F_MID) {
                    float* An = As + (buf ^ 1) * 8320 + (akv * 4) * 260 + ar;
                    An[0]         = pa0.x;  An[260]       = pa0.y;
                    An[520]       = pa0.z;  An[780]       = pa0.w;
                    An[128]       = pa1.x;  An[260 + 128] = pa1.y;
                    An[520 + 128] = pa1.z;  An[780 + 128] = pa1.w;
                    __syncthreads();
                    buf ^= 1;
                }
            }
#pragma unroll
            for (int i = 0; i < 4; i++) {
                int gr = rowBase + ty * 4 + i;
                if (gr < n) {
                    float2 lo = unpack2(acc2[i][0]);
                    float2 hi = unpack2(acc2[i][1]);
                    *(float4*)&g_HW2[(size_t)gr * F_OUT + tx * 4] =
                        make_float4(lo.x, lo.y, hi.x, hi.y);
                }
            }
        }
    }
    gbar();

    // ---- phase I: SPMM2  out = Ahat @ g_HW2 ----
    {
        const float2* base = (const float2*)g_HW2;     // row stride 32 f2
        const int gw = bid * 32 + wid;
        for (int row = gw; row < n; row += NWARPS) {
            int s = g_rowptr[row];
            int e = g_rowptr[row + 1];
            float2 acc = make_float2(0.f, 0.f);
            int i = s;
            for (; i + 7 < e; i += 8) {
                float2 cw[8];
#pragma unroll
                for (int u = 0; u < 8; u++) cw[u] = __ldg(&g_cw[i + u]);
                float2 vv[8];
#pragma unroll
                for (int u = 0; u < 8; u++)
                    vv[u] = __ldg(&base[((unsigned)__float_as_int(cw[u].x) << 5) + lane]);
#pragma unroll
                for (int u = 0; u < 8; u++) {
                    acc.x += cw[u].y * vv[u].x;
                    acc.y += cw[u].y * vv[u].y;
                }
            }
            if (i + 3 < e) {
                float2 cw[4];
#pragma unroll
                for (int u = 0; u < 4; u++) cw[u] = __ldg(&g_cw[i + u]);
                float2 vv[4];
#pragma unroll
                for (int u = 0; u < 4; u++)
                    vv[u] = __ldg(&base[((unsigned)__float_as_int(cw[u].x) << 5) + lane]);
#pragma unroll
                for (int u = 0; u < 4; u++) {
                    acc.x += cw[u].y * vv[u].x;
                    acc.y += cw[u].y * vv[u].y;
                }
                i += 4;
            }
            for (; i < e; i++) {
                float2 cw = __ldg(&g_cw[i]);
                float2 vv = __ldg(&base[((unsigned)__float_as_int(cw.x) << 5) + lane]);
                acc.x += cw.y * vv.x;
                acc.y += cw.y * vv.y;
            }
            ((float2*)out)[(unsigned)row * 32u + lane] = acc;
        }
    }
}

// ---------------- launch: ONE kernel, dynamic smem ----------------
extern "C" void kernel_launch(void* const* d_in, const int* in_sizes, int n_in,
                              void* d_out, int out_size) {
    const float* X  = (const float*)d_in[0];
    const float* W1 = (const float*)d_in[1];
    const float* W2 = (const float*)d_in[2];
    const int* erow = (const int*)d_in[3];
    const int* ecol = (const int*)d_in[4];
    const int E = in_sizes[3];
    const int n = in_sizes[0] / F_IN;
    float* out = (float*)d_out;

    cudaFuncSetAttribute(k_gcn, cudaFuncAttributeMaxDynamicSharedMemorySize,
                         SMEM_BYTES);
    k_gcn<<<NBLK, NTHR, SMEM_BYTES>>>(X, W1, W2, erow, ecol, E, n, out);
}